// round 5
// baseline (speedup 1.0000x reference)
#include <cuda_runtime.h>
#include <math.h>

#define J 20
#define JPS 5
#define F4PJ 16   // float4s per joint in sC4
// f4[0..8]  : (M0[i], M1[i], M2[i], i<3 ? p_rev[i] : 0)
// f4[9..11] : (Rpri row r, v_pri[r])
// f4[12]    : (p_pri[0..2], 0)
// f4[13..15]: (Rtrk row r, p_trk[r])

__device__ __forceinline__ void rpy2r_fast(float r, float p, float y, float* R) {
    float cr, sr, cp, sp, cy, sy;
    __sincosf(r, &sr, &cr);
    __sincosf(p, &sp, &cp);
    __sincosf(y, &sy, &cy);
    R[0] = cy * cp; R[1] = cy * sp * sr - sy * cr; R[2] = cy * sp * cr + sy * sr;
    R[3] = sy * cp; R[4] = sy * sp * sr + cy * cr; R[5] = sy * sp * cr - cy * sr;
    R[6] = -sp;     R[7] = cp * sr;                R[8] = cp * cr;
}

__device__ __forceinline__ void mm3(float* D, const float* A, const float* B) {
#pragma unroll
    for (int r = 0; r < 3; r++)
#pragma unroll
        for (int c = 0; c < 3; c++)
            D[r * 3 + c] = fmaf(A[r * 3 + 0], B[0 * 3 + c],
                           fmaf(A[r * 3 + 1], B[1 * 3 + c],
                                A[r * 3 + 2] * B[2 * 3 + c]));
}

// joint apply, vectorized constants. Updates (R,p) to post-prismatic; outputs rev frame (R1,p1).
__device__ __forceinline__ void joint_apply_v(const float4* __restrict__ C,
                                              float s, float ic, float qp,
                                              float R[9], float p[3],
                                              float R1[9], float p1[3]) {
    float Rs[9], prev[3];
#pragma unroll
    for (int i = 0; i < 9; i++) {
        float4 f = C[i];
        Rs[i] = fmaf(s, f.y, fmaf(ic, f.z, f.x));
        if (i < 3) prev[i] = f.w;
    }
    mm3(R1, R, Rs);
#pragma unroll
    for (int r = 0; r < 3; r++)
        p1[r] = fmaf(R[r*3+0], prev[0], fmaf(R[r*3+1], prev[1], fmaf(R[r*3+2], prev[2], p[r])));
    float4 b0 = C[9], b1 = C[10], b2 = C[11], pq = C[12];
    float ps0 = fmaf(qp, b0.w, pq.x);
    float ps1 = fmaf(qp, b1.w, pq.y);
    float ps2 = fmaf(qp, b2.w, pq.z);
    float R2[9];
#pragma unroll
    for (int r = 0; r < 3; r++) {
        R2[r*3+0] = fmaf(R1[r*3+0], b0.x, fmaf(R1[r*3+1], b1.x, R1[r*3+2] * b2.x));
        R2[r*3+1] = fmaf(R1[r*3+0], b0.y, fmaf(R1[r*3+1], b1.y, R1[r*3+2] * b2.y));
        R2[r*3+2] = fmaf(R1[r*3+0], b0.z, fmaf(R1[r*3+1], b1.z, R1[r*3+2] * b2.z));
    }
#pragma unroll
    for (int r = 0; r < 3; r++)
        p[r] = fmaf(R1[r*3+0], ps0, fmaf(R1[r*3+1], ps1, fmaf(R1[r*3+2], ps2, p1[r])));
#pragma unroll
    for (int i = 0; i < 9; i++) R[i] = R2[i];
}

// ---- generic (clamped) emit fallback for tail blocks ----
__device__ __forceinline__ void emit_full_g(float* stg, int lane, int i, int wb0, int B,
                                            float* __restrict__ tbase,
                                            const float R[9], const float p[3]) {
    float4* sp = (float4*)(stg + lane * 24);
    sp[0] = make_float4(R[0], R[1], R[2], p[0]);
    sp[1] = make_float4(R[3], R[4], R[5], p[1]);
    sp[2] = make_float4(R[6], R[7], R[8], p[2]);
    __syncwarp();
#pragma unroll
    for (int k = 0; k < 4; k++) {
        int c = k * 32 + lane, idx = c >> 2, m = c & 3;
        int bb = idx >> 2, s2 = idx & 3;
        int gb = wb0 + bb; if (gb >= B) gb = B - 1;
        float4 v = (m < 3) ? *(const float4*)(stg + idx * 24 + 4 * m)
                           : make_float4(0.f, 0.f, 0.f, 1.f);
        *(float4*)(tbase + ((size_t)gb * J + 5 * s2 + i) * 16 + 4 * m) = v;
    }
    __syncwarp();
}

__device__ __forceinline__ void emit_track_g(float* stg, int lane, int i, int wb0, int B,
                                             float* __restrict__ tbase,
                                             const float R[9], const float p[3], bool owner) {
    if (owner) {
        float4* sp = (float4*)(stg + lane * 24);
        sp[0] = make_float4(R[0], R[1], R[2], p[0]);
        sp[1] = make_float4(R[3], R[4], R[5], p[1]);
        sp[2] = make_float4(R[6], R[7], R[8], p[2]);
    }
    __syncwarp();
#pragma unroll
    for (int k = 0; k < 2; k++) {
        int c = k * 32 + lane, idx16 = c >> 2, m = c & 3;
        int bb = idx16 >> 1, pos = idx16 & 1;
        int s2 = (i & 1) + 2 * pos;
        int src = bb * 4 + s2;
        int slot = (5 * s2 + i) >> 1;
        int gb = wb0 + bb; if (gb >= B) gb = B - 1;
        float4 v = (m < 3) ? *(const float4*)(stg + src * 24 + 4 * m)
                           : make_float4(0.f, 0.f, 0.f, 1.f);
        *(float4*)(tbase + ((size_t)gb * (J / 2) + slot) * 16 + 4 * m) = v;
    }
    __syncwarp();
}

__global__ void __launch_bounds__(128, 7)
fk_kernel(const float* __restrict__ rev_q, const float* __restrict__ pri_q,
          const float* __restrict__ rev_p_off, const float* __restrict__ rev_rpy_off,
          const float* __restrict__ pri_p_off, const float* __restrict__ pri_rpy_off,
          const float* __restrict__ rev_axis, const float* __restrict__ pri_axis,
          const float* __restrict__ p_track, const float* __restrict__ rpy_track,
          float* __restrict__ out, int B) {
    __shared__ float4 sC4[J * F4PJ];
    __shared__ float sStage[4][32 * 24];

    int tid  = threadIdx.x;
    int lane = tid & 31;
    int w    = tid >> 5;
    int bb   = lane >> 2;
    int s    = lane & 3;
    int wb0  = blockIdx.x * 32 + w * 8;
    int gb   = wb0 + bb; if (gb >= B) gb = B - 1;

    // q loads + trig early
    float sn[JPS], ic[JPS], qp[JPS];
#pragma unroll
    for (int i = 0; i < JPS; i++) {
        float q = rev_q[(size_t)gb * J + s * JPS + i];
        float c;
        __sincosf(q, &sn[i], &c);
        ic[i] = 1.f - c;
        qp[i] = pri_q[(size_t)gb * J + s * JPS + i];
    }

    // ---- in-block constant prep (threads 0..19) ----
    if (tid < J) {
        int j = tid;
        float4* C = sC4 + j * F4PJ;
        float Ro[9];
        rpy2r_fast(rev_rpy_off[j*3+0], rev_rpy_off[j*3+1], rev_rpy_off[j*3+2], Ro);
        float ax = rev_axis[j*3+0], ay = rev_axis[j*3+1], az = rev_axis[j*3+2];
        float n = sqrtf(ax*ax + ay*ay + az*az) + 1e-12f;
        ax /= n; ay /= n; az /= n;
        float K[9]  = {0.f, -az, ay,  az, 0.f, -ax,  -ay, ax, 0.f};
        float K2[9]; mm3(K2, K, K);
        float M1[9], M2[9]; mm3(M1, Ro, K); mm3(M2, Ro, K2);
        float pr[3] = {rev_p_off[j*3+0], rev_p_off[j*3+1], rev_p_off[j*3+2]};
#pragma unroll
        for (int i = 0; i < 9; i++)
            C[i] = make_float4(Ro[i], M1[i], M2[i], i < 3 ? pr[i] : 0.f);

        float Rp[9];
        rpy2r_fast(pri_rpy_off[j*3+0], pri_rpy_off[j*3+1], pri_rpy_off[j*3+2], Rp);
        float pax = pri_axis[j*3+0], pay = pri_axis[j*3+1], paz = pri_axis[j*3+2];
#pragma unroll
        for (int r = 0; r < 3; r++) {
            float v = Rp[r*3+0]*pax + Rp[r*3+1]*pay + Rp[r*3+2]*paz;
            C[9 + r] = make_float4(Rp[r*3+0], Rp[r*3+1], Rp[r*3+2], v);
        }
        C[12] = make_float4(pri_p_off[j*3+0], pri_p_off[j*3+1], pri_p_off[j*3+2], 0.f);

        float Rt[9];
        rpy2r_fast(rpy_track[j*3+0], rpy_track[j*3+1], rpy_track[j*3+2], Rt);
#pragma unroll
        for (int r = 0; r < 3; r++)
            C[13 + r] = make_float4(Rt[r*3+0], Rt[r*3+1], Rt[r*3+2], p_track[j*3+r]);
    }
    __syncthreads();

    // ---- phase 1: local segment product ----
    float R[9] = {1.f,0.f,0.f, 0.f,1.f,0.f, 0.f,0.f,1.f};
    float p[3] = {0.f, 0.f, 0.f};
#pragma unroll
    for (int i = 0; i < JPS; i++) {
        const float4* C = sC4 + (s * JPS + i) * F4PJ;
        float R1[9], p1[3];
        joint_apply_v(C, sn[i], ic[i], qp[i], R, p, R1, p1);
    }

    // ---- phase 2: exclusive prefix within 4-lane group via shfl ----
    float P[9] = {1.f,0.f,0.f, 0.f,1.f,0.f, 0.f,0.f,1.f};
    float pp[3] = {0.f, 0.f, 0.f};
    int base = lane & ~3;
#pragma unroll
    for (int k = 0; k < 3; k++) {
        float Lr[9], Lp[3];
#pragma unroll
        for (int t = 0; t < 9; t++) Lr[t] = __shfl_sync(0xffffffffu, R[t], base + k);
#pragma unroll
        for (int t = 0; t < 3; t++) Lp[t] = __shfl_sync(0xffffffffu, p[t], base + k);
        if (k < s) {
            float pn[3];
#pragma unroll
            for (int r = 0; r < 3; r++)
                pn[r] = fmaf(P[r*3+0], Lp[0],
                        fmaf(P[r*3+1], Lp[1],
                        fmaf(P[r*3+2], Lp[2], pp[r])));
            float Rn[9];
            mm3(Rn, P, Lr);
#pragma unroll
            for (int t = 0; t < 9; t++) P[t] = Rn[t];
            pp[0] = pn[0]; pp[1] = pn[1]; pp[2] = pn[2];
        }
    }

    // ---- phase 3: re-run from prefix, emitting ----
    float* stg = sStage[w];
    float* outTrk = out;
    float* outRev = out + (size_t)B * 160;
    float* outPri = out + (size_t)B * 480;

#pragma unroll
    for (int t = 0; t < 9; t++) R[t] = P[t];
    p[0] = pp[0]; p[1] = pp[1]; p[2] = pp[2];

    bool fast = (wb0 + 32 <= B);

    // per-lane invariants for fast emit
    int u  = lane >> 2;
    int m  = lane & 3;
    int ub = u >> 2;       // 0..1
    int s2 = u & 3;        // source segment for full drains
    int uh = u >> 1;       // 0..3 (track)
    int up = u & 1;        // track pos
    float* baseRev = outRev + ((size_t)(wb0 + ub) * J + 5 * s2) * 16 + 4 * m;
    float* basePri = outPri + ((size_t)(wb0 + ub) * J + 5 * s2) * 16 + 4 * m;
    const float4 hom = make_float4(0.f, 0.f, 0.f, 1.f);

#pragma unroll
    for (int i = 0; i < JPS; i++) {
        int j = s * JPS + i;
        const float4* C = sC4 + j * F4PJ;
        float R1[9], p1[3];
        joint_apply_v(C, sn[i], ic[i], qp[i], R, p, R1, p1);

        bool owner = (((s ^ i) & 1) == 0);
        float Rt[9] = {0}, pt[3] = {0};
        if (owner) {
            float4 t0 = C[13], t1 = C[14], t2 = C[15];
#pragma unroll
            for (int r = 0; r < 3; r++) {
                Rt[r*3+0] = fmaf(R[r*3+0], t0.x, fmaf(R[r*3+1], t1.x, R[r*3+2] * t2.x));
                Rt[r*3+1] = fmaf(R[r*3+0], t0.y, fmaf(R[r*3+1], t1.y, R[r*3+2] * t2.y));
                Rt[r*3+2] = fmaf(R[r*3+0], t0.z, fmaf(R[r*3+1], t1.z, R[r*3+2] * t2.z));
                pt[r] = fmaf(R[r*3+0], t0.w, fmaf(R[r*3+1], t1.w, fmaf(R[r*3+2], t2.w, p[r])));
            }
        }

        if (fast) {
            // stage rev + pri together
            float4* sp = (float4*)(stg + lane * 24);
            sp[0] = make_float4(R1[0], R1[1], R1[2], p1[0]);
            sp[1] = make_float4(R1[3], R1[4], R1[5], p1[1]);
            sp[2] = make_float4(R1[6], R1[7], R1[8], p1[2]);
            sp[3] = make_float4(R[0], R[1], R[2], p[0]);
            sp[4] = make_float4(R[3], R[4], R[5], p[1]);
            sp[5] = make_float4(R[6], R[7], R[8], p[2]);
            __syncwarp();
            float* dR = baseRev + i * 16;
            float* dP = basePri + i * 16;
#pragma unroll
            for (int k = 0; k < 4; k++) {
                const float* src = stg + (k * 8 + u) * 24 + 4 * m;
                float4 vr = (m < 3) ? *(const float4*)src        : hom;
                float4 vp = (m < 3) ? *(const float4*)(src + 12) : hom;
                *(float4*)(dR + k * 640) = vr;
                *(float4*)(dP + k * 640) = vp;
            }
            __syncwarp();
            if ((j & 1) == 0) {   // tracking joint (j even <=> owner parity handled by s2t)
                if (owner) {
                    float4* tp = (float4*)(stg + lane * 24);
                    tp[0] = make_float4(Rt[0], Rt[1], Rt[2], pt[0]);
                    tp[1] = make_float4(Rt[3], Rt[4], Rt[5], pt[1]);
                    tp[2] = make_float4(Rt[6], Rt[7], Rt[8], pt[2]);
                }
            }
            // NOTE: track drain must run for all i (two owner segments per i)
            {
                int s2t  = (i & 1) + 2 * up;
                int slot = (5 * s2t + i) >> 1;
                // ensure owner writes visible
                __syncwarp();
                float* dT = outTrk + ((size_t)(wb0 + uh) * 10 + slot) * 16 + 4 * m;
#pragma unroll
                for (int k = 0; k < 2; k++) {
                    const float* src = stg + (16 * k + uh * 4 + s2t) * 24 + 4 * m;
                    float4 v = (m < 3) ? *(const float4*)src : hom;
                    *(float4*)(dT + k * 640) = v;
                }
                __syncwarp();
            }
        } else {
            emit_full_g(stg, lane, i, wb0, B, outRev, R1, p1);
            emit_full_g(stg, lane, i, wb0, B, outPri, R, p);
            emit_track_g(stg, lane, i, wb0, B, outTrk, Rt, pt, owner);
        }
    }
}

extern "C" void kernel_launch(void* const* d_in, const int* in_sizes, int n_in,
                              void* d_out, int out_size) {
    const float* rev_q       = (const float*)d_in[0];
    const float* pri_q       = (const float*)d_in[1];
    const float* rev_p_off   = (const float*)d_in[2];
    const float* rev_rpy_off = (const float*)d_in[3];
    const float* pri_p_off   = (const float*)d_in[4];
    const float* pri_rpy_off = (const float*)d_in[5];
    const float* rev_axis    = (const float*)d_in[6];
    const float* pri_axis    = (const float*)d_in[7];
    const float* p_track     = (const float*)d_in[8];
    const float* rpy_track   = (const float*)d_in[9];
    float* out = (float*)d_out;

    int B = in_sizes[0] / J;
    int grid = (B + 31) / 32;
    fk_kernel<<<grid, 128>>>(rev_q, pri_q,
                             rev_p_off, rev_rpy_off, pri_p_off, pri_rpy_off,
                             rev_axis, pri_axis, p_track, rpy_track, out, B);
}

// round 6
// speedup vs baseline: 1.0726x; 1.0726x over previous
#include <cuda_runtime.h>
#include <math.h>

#define J 20
#define JPS 5
#define F4PJ 16   // float4s per joint in sC4
// f4[0..8]  : (M0[i], M1[i], M2[i], i<3 ? p_rev[i] : 0)
// f4[9..11] : (Rpri row r, v_pri[r])
// f4[12]    : (p_pri[0..2], 0)
// f4[13..15]: (Rtrk row r, p_trk[r])

__device__ __forceinline__ void rpy2r_fast(float r, float p, float y, float* R) {
    float cr, sr, cp, sp, cy, sy;
    __sincosf(r, &sr, &cr);
    __sincosf(p, &sp, &cp);
    __sincosf(y, &sy, &cy);
    R[0] = cy * cp; R[1] = cy * sp * sr - sy * cr; R[2] = cy * sp * cr + sy * sr;
    R[3] = sy * cp; R[4] = sy * sp * sr + cy * cr; R[5] = sy * sp * cr - cy * sr;
    R[6] = -sp;     R[7] = cp * sr;                R[8] = cp * cr;
}

__device__ __forceinline__ void mm3(float* D, const float* A, const float* B) {
#pragma unroll
    for (int r = 0; r < 3; r++)
#pragma unroll
        for (int c = 0; c < 3; c++)
            D[r * 3 + c] = fmaf(A[r * 3 + 0], B[0 * 3 + c],
                           fmaf(A[r * 3 + 1], B[1 * 3 + c],
                                A[r * 3 + 2] * B[2 * 3 + c]));
}

// joint apply with vectorized constants (13 LDS.128 per call)
__device__ __forceinline__ void joint_apply_v(const float4* __restrict__ C,
                                              float s, float ic, float qp,
                                              float R[9], float p[3],
                                              float R1[9], float p1[3]) {
    float Rs[9], prev[3];
#pragma unroll
    for (int i = 0; i < 9; i++) {
        float4 f = C[i];
        Rs[i] = fmaf(s, f.y, fmaf(ic, f.z, f.x));
        if (i < 3) prev[i] = f.w;
    }
    mm3(R1, R, Rs);
#pragma unroll
    for (int r = 0; r < 3; r++)
        p1[r] = fmaf(R[r*3+0], prev[0], fmaf(R[r*3+1], prev[1], fmaf(R[r*3+2], prev[2], p[r])));
    float4 b0 = C[9], b1 = C[10], b2 = C[11], pq = C[12];
    float ps0 = fmaf(qp, b0.w, pq.x);
    float ps1 = fmaf(qp, b1.w, pq.y);
    float ps2 = fmaf(qp, b2.w, pq.z);
    float R2[9];
#pragma unroll
    for (int r = 0; r < 3; r++) {
        R2[r*3+0] = fmaf(R1[r*3+0], b0.x, fmaf(R1[r*3+1], b1.x, R1[r*3+2] * b2.x));
        R2[r*3+1] = fmaf(R1[r*3+0], b0.y, fmaf(R1[r*3+1], b1.y, R1[r*3+2] * b2.y));
        R2[r*3+2] = fmaf(R1[r*3+0], b0.z, fmaf(R1[r*3+1], b1.z, R1[r*3+2] * b2.z));
    }
#pragma unroll
    for (int r = 0; r < 3; r++)
        p[r] = fmaf(R1[r*3+0], ps0, fmaf(R1[r*3+1], ps1, fmaf(R1[r*3+2], ps2, p1[r])));
#pragma unroll
    for (int i = 0; i < 9; i++) R[i] = R2[i];
}

// ---- generic (clamped) emits for tail blocks; 12-float stride staging ----
__device__ __forceinline__ void emit_full_g(float* stg, int lane, int i, int wb0, int B,
                                            float* __restrict__ tbase,
                                            const float R[9], const float p[3]) {
    float4* sp = (float4*)(stg + lane * 12);
    sp[0] = make_float4(R[0], R[1], R[2], p[0]);
    sp[1] = make_float4(R[3], R[4], R[5], p[1]);
    sp[2] = make_float4(R[6], R[7], R[8], p[2]);
    __syncwarp();
#pragma unroll
    for (int k = 0; k < 4; k++) {
        int c = k * 32 + lane, idx = c >> 2, m = c & 3;
        int bb = idx >> 2, s2 = idx & 3;
        int gb = wb0 + bb; if (gb >= B) gb = B - 1;
        float4 v = (m < 3) ? *(const float4*)(stg + idx * 12 + 4 * m)
                           : make_float4(0.f, 0.f, 0.f, 1.f);
        *(float4*)(tbase + ((size_t)gb * J + 5 * s2 + i) * 16 + 4 * m) = v;
    }
    __syncwarp();
}

__device__ __forceinline__ void emit_track_g(float* stg, int lane, int i, int wb0, int B,
                                             float* __restrict__ tbase,
                                             const float R[9], const float p[3], bool owner) {
    if (owner) {
        float4* sp = (float4*)(stg + lane * 12);
        sp[0] = make_float4(R[0], R[1], R[2], p[0]);
        sp[1] = make_float4(R[3], R[4], R[5], p[1]);
        sp[2] = make_float4(R[6], R[7], R[8], p[2]);
    }
    __syncwarp();
#pragma unroll
    for (int k = 0; k < 2; k++) {
        int c = k * 32 + lane, idx16 = c >> 2, m = c & 3;
        int bb = idx16 >> 1, pos = idx16 & 1;
        int s2 = (i & 1) + 2 * pos;
        int src = bb * 4 + s2;
        int slot = (5 * s2 + i) >> 1;
        int gb = wb0 + bb; if (gb >= B) gb = B - 1;
        float4 v = (m < 3) ? *(const float4*)(stg + src * 12 + 4 * m)
                           : make_float4(0.f, 0.f, 0.f, 1.f);
        *(float4*)(tbase + ((size_t)gb * (J / 2) + slot) * 16 + 4 * m) = v;
    }
    __syncwarp();
}

__global__ void __launch_bounds__(128, 7)
fk_kernel(const float* __restrict__ rev_q, const float* __restrict__ pri_q,
          const float* __restrict__ rev_p_off, const float* __restrict__ rev_rpy_off,
          const float* __restrict__ pri_p_off, const float* __restrict__ pri_rpy_off,
          const float* __restrict__ rev_axis, const float* __restrict__ pri_axis,
          const float* __restrict__ p_track, const float* __restrict__ rpy_track,
          float* __restrict__ out, int B) {
    __shared__ float4 sC4[J * F4PJ];
    __shared__ float sStage[4][2 * 32 * 12];   // rev @0, pri @384 — both 12-stride

    int tid  = threadIdx.x;
    int lane = tid & 31;
    int w    = tid >> 5;
    int bb   = lane >> 2;
    int s    = lane & 3;
    int wb0  = blockIdx.x * 32 + w * 8;
    int gb   = wb0 + bb; if (gb >= B) gb = B - 1;

    // q loads + trig early
    float sn[JPS], ic[JPS], qp[JPS];
#pragma unroll
    for (int i = 0; i < JPS; i++) {
        float q = rev_q[(size_t)gb * J + s * JPS + i];
        float c;
        __sincosf(q, &sn[i], &c);
        ic[i] = 1.f - c;
        qp[i] = pri_q[(size_t)gb * J + s * JPS + i];
    }

    // ---- in-block constant prep (threads 0..19) ----
    if (tid < J) {
        int j = tid;
        float4* C = sC4 + j * F4PJ;
        float Ro[9];
        rpy2r_fast(rev_rpy_off[j*3+0], rev_rpy_off[j*3+1], rev_rpy_off[j*3+2], Ro);
        float ax = rev_axis[j*3+0], ay = rev_axis[j*3+1], az = rev_axis[j*3+2];
        float n = sqrtf(ax*ax + ay*ay + az*az) + 1e-12f;
        ax /= n; ay /= n; az /= n;
        float K[9]  = {0.f, -az, ay,  az, 0.f, -ax,  -ay, ax, 0.f};
        float K2[9]; mm3(K2, K, K);
        float M1[9], M2[9]; mm3(M1, Ro, K); mm3(M2, Ro, K2);
        float pr[3] = {rev_p_off[j*3+0], rev_p_off[j*3+1], rev_p_off[j*3+2]};
#pragma unroll
        for (int i = 0; i < 9; i++)
            C[i] = make_float4(Ro[i], M1[i], M2[i], i < 3 ? pr[i] : 0.f);

        float Rp[9];
        rpy2r_fast(pri_rpy_off[j*3+0], pri_rpy_off[j*3+1], pri_rpy_off[j*3+2], Rp);
        float pax = pri_axis[j*3+0], pay = pri_axis[j*3+1], paz = pri_axis[j*3+2];
#pragma unroll
        for (int r = 0; r < 3; r++) {
            float v = Rp[r*3+0]*pax + Rp[r*3+1]*pay + Rp[r*3+2]*paz;
            C[9 + r] = make_float4(Rp[r*3+0], Rp[r*3+1], Rp[r*3+2], v);
        }
        C[12] = make_float4(pri_p_off[j*3+0], pri_p_off[j*3+1], pri_p_off[j*3+2], 0.f);

        float Rt[9];
        rpy2r_fast(rpy_track[j*3+0], rpy_track[j*3+1], rpy_track[j*3+2], Rt);
#pragma unroll
        for (int r = 0; r < 3; r++)
            C[13 + r] = make_float4(Rt[r*3+0], Rt[r*3+1], Rt[r*3+2], p_track[j*3+r]);
    }
    __syncthreads();

    // ---- phase 1: local segment product ----
    float R[9] = {1.f,0.f,0.f, 0.f,1.f,0.f, 0.f,0.f,1.f};
    float p[3] = {0.f, 0.f, 0.f};
#pragma unroll
    for (int i = 0; i < JPS; i++) {
        const float4* C = sC4 + (s * JPS + i) * F4PJ;
        float R1[9], p1[3];
        joint_apply_v(C, sn[i], ic[i], qp[i], R, p, R1, p1);
    }

    // ---- phase 2: exclusive prefix within 4-lane group via shfl ----
    float P[9] = {1.f,0.f,0.f, 0.f,1.f,0.f, 0.f,0.f,1.f};
    float pp[3] = {0.f, 0.f, 0.f};
    int base = lane & ~3;
#pragma unroll
    for (int k = 0; k < 3; k++) {
        float Lr[9], Lp[3];
#pragma unroll
        for (int t = 0; t < 9; t++) Lr[t] = __shfl_sync(0xffffffffu, R[t], base + k);
#pragma unroll
        for (int t = 0; t < 3; t++) Lp[t] = __shfl_sync(0xffffffffu, p[t], base + k);
        if (k < s) {
            float pn[3];
#pragma unroll
            for (int r = 0; r < 3; r++)
                pn[r] = fmaf(P[r*3+0], Lp[0],
                        fmaf(P[r*3+1], Lp[1],
                        fmaf(P[r*3+2], Lp[2], pp[r])));
            float Rn[9];
            mm3(Rn, P, Lr);
#pragma unroll
            for (int t = 0; t < 9; t++) P[t] = Rn[t];
            pp[0] = pn[0]; pp[1] = pn[1]; pp[2] = pn[2];
        }
    }

    // ---- phase 3: re-run from prefix, emitting ----
    float* stg  = sStage[w];        // rev region
    float* stgP = sStage[w] + 384;  // pri region
    float* outTrk = out;
    float* outRev = out + (size_t)B * 160;
    float* outPri = out + (size_t)B * 480;

#pragma unroll
    for (int t = 0; t < 9; t++) R[t] = P[t];
    p[0] = pp[0]; p[1] = pp[1]; p[2] = pp[2];

    bool fast = (wb0 + 32 <= B);

    // per-lane drain invariants
    int u  = lane >> 2;    // 0..7
    int m  = lane & 3;     // quad
    int ub = u >> 2;       // 0..1 (full drains)
    int s2 = u & 3;
    int uh = u >> 1;       // 0..3 (track)
    int up = u & 1;
    float* baseRev = outRev + ((size_t)(wb0 + ub) * J + 5 * s2) * 16 + 4 * m;
    float* basePri = outPri + ((size_t)(wb0 + ub) * J + 5 * s2) * 16 + 4 * m;
    const float4 hom = make_float4(0.f, 0.f, 0.f, 1.f);

#pragma unroll
    for (int i = 0; i < JPS; i++) {
        int j = s * JPS + i;
        const float4* C = sC4 + j * F4PJ;
        float R1[9], p1[3];
        joint_apply_v(C, sn[i], ic[i], qp[i], R, p, R1, p1);

        bool owner = (((s ^ i) & 1) == 0);
        float Rt[9] = {0}, pt[3] = {0};
        if (owner) {
            float4 t0 = C[13], t1 = C[14], t2 = C[15];
#pragma unroll
            for (int r = 0; r < 3; r++) {
                Rt[r*3+0] = fmaf(R[r*3+0], t0.x, fmaf(R[r*3+1], t1.x, R[r*3+2] * t2.x));
                Rt[r*3+1] = fmaf(R[r*3+0], t0.y, fmaf(R[r*3+1], t1.y, R[r*3+2] * t2.y));
                Rt[r*3+2] = fmaf(R[r*3+0], t0.z, fmaf(R[r*3+1], t1.z, R[r*3+2] * t2.z));
                pt[r] = fmaf(R[r*3+0], t0.w, fmaf(R[r*3+1], t1.w, fmaf(R[r*3+2], t2.w, p[r])));
            }
        }

        if (fast) {
            // stage rev and pri in separate conflict-free 12-stride regions
            float4* spR = (float4*)(stg  + lane * 12);
            float4* spP = (float4*)(stgP + lane * 12);
            spR[0] = make_float4(R1[0], R1[1], R1[2], p1[0]);
            spR[1] = make_float4(R1[3], R1[4], R1[5], p1[1]);
            spR[2] = make_float4(R1[6], R1[7], R1[8], p1[2]);
            spP[0] = make_float4(R[0], R[1], R[2], p[0]);
            spP[1] = make_float4(R[3], R[4], R[5], p[1]);
            spP[2] = make_float4(R[6], R[7], R[8], p[2]);
            __syncwarp();
            float* dR = baseRev + i * 16;
            float* dP = basePri + i * 16;
#pragma unroll
            for (int k = 0; k < 4; k++) {
                int idx = k * 8 + u;
                float4 vr = (m < 3) ? *(const float4*)(stg  + idx * 12 + 4 * m) : hom;
                float4 vp = (m < 3) ? *(const float4*)(stgP + idx * 12 + 4 * m) : hom;
                *(float4*)(dR + k * 640) = vr;
                *(float4*)(dP + k * 640) = vp;
            }
            __syncwarp();
            // track: owners overwrite rev region, then 2-phase drain
            if (owner) {
                float4* tp = (float4*)(stg + lane * 12);
                tp[0] = make_float4(Rt[0], Rt[1], Rt[2], pt[0]);
                tp[1] = make_float4(Rt[3], Rt[4], Rt[5], pt[1]);
                tp[2] = make_float4(Rt[6], Rt[7], Rt[8], pt[2]);
            }
            __syncwarp();
            {
                int s2t  = (i & 1) + 2 * up;
                int slot = (5 * s2t + i) >> 1;
                float* dT = outTrk + ((size_t)(wb0 + uh) * 10 + slot) * 16 + 4 * m;
#pragma unroll
                for (int k = 0; k < 2; k++) {
                    int src = (k * 4 + uh) * 4 + s2t;
                    float4 v = (m < 3) ? *(const float4*)(stg + src * 12 + 4 * m) : hom;
                    *(float4*)(dT + k * 640) = v;
                }
            }
            __syncwarp();
        } else {
            emit_full_g(stg, lane, i, wb0, B, outRev, R1, p1);
            emit_full_g(stg, lane, i, wb0, B, outPri, R, p);
            emit_track_g(stg, lane, i, wb0, B, outTrk, Rt, pt, owner);
        }
    }
}

extern "C" void kernel_launch(void* const* d_in, const int* in_sizes, int n_in,
                              void* d_out, int out_size) {
    const float* rev_q       = (const float*)d_in[0];
    const float* pri_q       = (const float*)d_in[1];
    const float* rev_p_off   = (const float*)d_in[2];
    const float* rev_rpy_off = (const float*)d_in[3];
    const float* pri_p_off   = (const float*)d_in[4];
    const float* pri_rpy_off = (const float*)d_in[5];
    const float* rev_axis    = (const float*)d_in[6];
    const float* pri_axis    = (const float*)d_in[7];
    const float* p_track     = (const float*)d_in[8];
    const float* rpy_track   = (const float*)d_in[9];
    float* out = (float*)d_out;

    int B = in_sizes[0] / J;
    int grid = (B + 31) / 32;
    fk_kernel<<<grid, 128>>>(rev_q, pri_q,
                             rev_p_off, rev_rpy_off, pri_p_off, pri_rpy_off,
                             rev_axis, pri_axis, p_track, rpy_track, out, B);
}

// round 7
// speedup vs baseline: 1.6226x; 1.5127x over previous
#include <cuda_runtime.h>
#include <math.h>

#define J 20
#define JPS 5
#define F4PJ 17   // float4s per joint in sC4 (ODD stride -> conflict-free broadcast)
// f4[0..8]  : (M0[i], M1[i], M2[i], i<3 ? p_rev[i] : 0)
// f4[9..11] : (Rpri row r, v_pri[r])
// f4[12]    : (p_pri[0..2], 0)
// f4[13..15]: (Rtrk row r, p_trk[r])
// f4[16]    : pad

__device__ __forceinline__ void rpy2r_fast(float r, float p, float y, float* R) {
    float cr, sr, cp, sp, cy, sy;
    __sincosf(r, &sr, &cr);
    __sincosf(p, &sp, &cp);
    __sincosf(y, &sy, &cy);
    R[0] = cy * cp; R[1] = cy * sp * sr - sy * cr; R[2] = cy * sp * cr + sy * sr;
    R[3] = sy * cp; R[4] = sy * sp * sr + cy * cr; R[5] = sy * sp * cr - cy * sr;
    R[6] = -sp;     R[7] = cp * sr;                R[8] = cp * cr;
}

__device__ __forceinline__ void mm3(float* D, const float* A, const float* B) {
#pragma unroll
    for (int r = 0; r < 3; r++)
#pragma unroll
        for (int c = 0; c < 3; c++)
            D[r * 3 + c] = fmaf(A[r * 3 + 0], B[0 * 3 + c],
                           fmaf(A[r * 3 + 1], B[1 * 3 + c],
                                A[r * 3 + 2] * B[2 * 3 + c]));
}

// joint apply with vectorized constants (13 LDS.128 per call)
__device__ __forceinline__ void joint_apply_v(const float4* __restrict__ C,
                                              float s, float ic, float qp,
                                              float R[9], float p[3],
                                              float R1[9], float p1[3]) {
    float Rs[9], prev[3];
#pragma unroll
    for (int i = 0; i < 9; i++) {
        float4 f = C[i];
        Rs[i] = fmaf(s, f.y, fmaf(ic, f.z, f.x));
        if (i < 3) prev[i] = f.w;
    }
    mm3(R1, R, Rs);
#pragma unroll
    for (int r = 0; r < 3; r++)
        p1[r] = fmaf(R[r*3+0], prev[0], fmaf(R[r*3+1], prev[1], fmaf(R[r*3+2], prev[2], p[r])));
    float4 b0 = C[9], b1 = C[10], b2 = C[11], pq = C[12];
    float ps0 = fmaf(qp, b0.w, pq.x);
    float ps1 = fmaf(qp, b1.w, pq.y);
    float ps2 = fmaf(qp, b2.w, pq.z);
    float R2[9];
#pragma unroll
    for (int r = 0; r < 3; r++) {
        R2[r*3+0] = fmaf(R1[r*3+0], b0.x, fmaf(R1[r*3+1], b1.x, R1[r*3+2] * b2.x));
        R2[r*3+1] = fmaf(R1[r*3+0], b0.y, fmaf(R1[r*3+1], b1.y, R1[r*3+2] * b2.y));
        R2[r*3+2] = fmaf(R1[r*3+0], b0.z, fmaf(R1[r*3+1], b1.z, R1[r*3+2] * b2.z));
    }
#pragma unroll
    for (int r = 0; r < 3; r++)
        p[r] = fmaf(R1[r*3+0], ps0, fmaf(R1[r*3+1], ps1, fmaf(R1[r*3+2], ps2, p1[r])));
#pragma unroll
    for (int i = 0; i < 9; i++) R[i] = R2[i];
}

// ---- generic (clamped) emits for tail blocks; 12-float stride staging ----
__device__ __forceinline__ void emit_full_g(float* stg, int lane, int i, int wb0, int B,
                                            float* __restrict__ tbase,
                                            const float R[9], const float p[3]) {
    float4* sp = (float4*)(stg + lane * 12);
    sp[0] = make_float4(R[0], R[1], R[2], p[0]);
    sp[1] = make_float4(R[3], R[4], R[5], p[1]);
    sp[2] = make_float4(R[6], R[7], R[8], p[2]);
    __syncwarp();
#pragma unroll
    for (int k = 0; k < 4; k++) {
        int c = k * 32 + lane, idx = c >> 2, m = c & 3;
        int bb = idx >> 2, s2 = idx & 3;
        int gb = wb0 + bb; if (gb >= B) gb = B - 1;
        float4 v = (m < 3) ? *(const float4*)(stg + idx * 12 + 4 * m)
                           : make_float4(0.f, 0.f, 0.f, 1.f);
        *(float4*)(tbase + ((size_t)gb * J + 5 * s2 + i) * 16 + 4 * m) = v;
    }
    __syncwarp();
}

__device__ __forceinline__ void emit_track_g(float* stg, int lane, int i, int wb0, int B,
                                             float* __restrict__ tbase,
                                             const float R[9], const float p[3], bool owner) {
    if (owner) {
        float4* sp = (float4*)(stg + lane * 12);
        sp[0] = make_float4(R[0], R[1], R[2], p[0]);
        sp[1] = make_float4(R[3], R[4], R[5], p[1]);
        sp[2] = make_float4(R[6], R[7], R[8], p[2]);
    }
    __syncwarp();
#pragma unroll
    for (int k = 0; k < 2; k++) {
        int c = k * 32 + lane, idx16 = c >> 2, m = c & 3;
        int bb = idx16 >> 1, pos = idx16 & 1;
        int s2 = (i & 1) + 2 * pos;
        int src = bb * 4 + s2;
        int slot = (5 * s2 + i) >> 1;
        int gb = wb0 + bb; if (gb >= B) gb = B - 1;
        float4 v = (m < 3) ? *(const float4*)(stg + src * 12 + 4 * m)
                           : make_float4(0.f, 0.f, 0.f, 1.f);
        *(float4*)(tbase + ((size_t)gb * (J / 2) + slot) * 16 + 4 * m) = v;
    }
    __syncwarp();
}

__global__ void __launch_bounds__(128, 7)
fk_kernel(const float* __restrict__ rev_q, const float* __restrict__ pri_q,
          const float* __restrict__ rev_p_off, const float* __restrict__ rev_rpy_off,
          const float* __restrict__ pri_p_off, const float* __restrict__ pri_rpy_off,
          const float* __restrict__ rev_axis, const float* __restrict__ pri_axis,
          const float* __restrict__ p_track, const float* __restrict__ rpy_track,
          float* __restrict__ out, int B) {
    __shared__ float4 sC4[J * F4PJ];
    __shared__ float sStage[4][2 * 32 * 12];   // rev @0, pri @384 — both 12-stride

    int tid  = threadIdx.x;
    int lane = tid & 31;
    int w    = tid >> 5;
    int bb   = lane >> 2;
    int s    = lane & 3;
    int wb0  = blockIdx.x * 32 + w * 8;
    int gb   = wb0 + bb; if (gb >= B) gb = B - 1;

    // q loads + trig early
    float sn[JPS], ic[JPS], qp[JPS];
#pragma unroll
    for (int i = 0; i < JPS; i++) {
        float q = rev_q[(size_t)gb * J + s * JPS + i];
        float c;
        __sincosf(q, &sn[i], &c);
        ic[i] = 1.f - c;
        qp[i] = pri_q[(size_t)gb * J + s * JPS + i];
    }

    // ---- in-block constant prep (threads 0..19) ----
    if (tid < J) {
        int j = tid;
        float4* C = sC4 + j * F4PJ;
        float Ro[9];
        rpy2r_fast(rev_rpy_off[j*3+0], rev_rpy_off[j*3+1], rev_rpy_off[j*3+2], Ro);
        float ax = rev_axis[j*3+0], ay = rev_axis[j*3+1], az = rev_axis[j*3+2];
        float n = sqrtf(ax*ax + ay*ay + az*az) + 1e-12f;
        ax /= n; ay /= n; az /= n;
        float K[9]  = {0.f, -az, ay,  az, 0.f, -ax,  -ay, ax, 0.f};
        float K2[9]; mm3(K2, K, K);
        float M1[9], M2[9]; mm3(M1, Ro, K); mm3(M2, Ro, K2);
        float pr[3] = {rev_p_off[j*3+0], rev_p_off[j*3+1], rev_p_off[j*3+2]};
#pragma unroll
        for (int i = 0; i < 9; i++)
            C[i] = make_float4(Ro[i], M1[i], M2[i], i < 3 ? pr[i] : 0.f);

        float Rp[9];
        rpy2r_fast(pri_rpy_off[j*3+0], pri_rpy_off[j*3+1], pri_rpy_off[j*3+2], Rp);
        float pax = pri_axis[j*3+0], pay = pri_axis[j*3+1], paz = pri_axis[j*3+2];
#pragma unroll
        for (int r = 0; r < 3; r++) {
            float v = Rp[r*3+0]*pax + Rp[r*3+1]*pay + Rp[r*3+2]*paz;
            C[9 + r] = make_float4(Rp[r*3+0], Rp[r*3+1], Rp[r*3+2], v);
        }
        C[12] = make_float4(pri_p_off[j*3+0], pri_p_off[j*3+1], pri_p_off[j*3+2], 0.f);

        float Rt[9];
        rpy2r_fast(rpy_track[j*3+0], rpy_track[j*3+1], rpy_track[j*3+2], Rt);
#pragma unroll
        for (int r = 0; r < 3; r++)
            C[13 + r] = make_float4(Rt[r*3+0], Rt[r*3+1], Rt[r*3+2], p_track[j*3+r]);
    }
    __syncthreads();

    // ---- phase 1: local segment product ----
    float R[9] = {1.f,0.f,0.f, 0.f,1.f,0.f, 0.f,0.f,1.f};
    float p[3] = {0.f, 0.f, 0.f};
#pragma unroll
    for (int i = 0; i < JPS; i++) {
        const float4* C = sC4 + (s * JPS + i) * F4PJ;
        float R1[9], p1[3];
        joint_apply_v(C, sn[i], ic[i], qp[i], R, p, R1, p1);
    }

    // ---- phase 2: exclusive prefix within 4-lane group via shfl ----
    float P[9] = {1.f,0.f,0.f, 0.f,1.f,0.f, 0.f,0.f,1.f};
    float pp[3] = {0.f, 0.f, 0.f};
    int base = lane & ~3;
#pragma unroll
    for (int k = 0; k < 3; k++) {
        float Lr[9], Lp[3];
#pragma unroll
        for (int t = 0; t < 9; t++) Lr[t] = __shfl_sync(0xffffffffu, R[t], base + k);
#pragma unroll
        for (int t = 0; t < 3; t++) Lp[t] = __shfl_sync(0xffffffffu, p[t], base + k);
        if (k < s) {
            float pn[3];
#pragma unroll
            for (int r = 0; r < 3; r++)
                pn[r] = fmaf(P[r*3+0], Lp[0],
                        fmaf(P[r*3+1], Lp[1],
                        fmaf(P[r*3+2], Lp[2], pp[r])));
            float Rn[9];
            mm3(Rn, P, Lr);
#pragma unroll
            for (int t = 0; t < 9; t++) P[t] = Rn[t];
            pp[0] = pn[0]; pp[1] = pn[1]; pp[2] = pn[2];
        }
    }

    // ---- phase 3: re-run from prefix, emitting ----
    float* stg  = sStage[w];        // rev region
    float* stgP = sStage[w] + 384;  // pri region
    float* outTrk = out;
    float* outRev = out + (size_t)B * 160;
    float* outPri = out + (size_t)B * 480;

#pragma unroll
    for (int t = 0; t < 9; t++) R[t] = P[t];
    p[0] = pp[0]; p[1] = pp[1]; p[2] = pp[2];

    bool fast = (wb0 + 32 <= B);

    // per-lane drain invariants
    int u  = lane >> 2;    // 0..7
    int m  = lane & 3;     // quad
    int ub = u >> 2;       // 0..1 (full drains)
    int s2 = u & 3;
    int uh = u >> 1;       // 0..3 (track)
    int up = u & 1;
    float* baseRev = outRev + ((size_t)(wb0 + ub) * J + 5 * s2) * 16 + 4 * m;
    float* basePri = outPri + ((size_t)(wb0 + ub) * J + 5 * s2) * 16 + 4 * m;
    const float4 hom = make_float4(0.f, 0.f, 0.f, 1.f);

#pragma unroll
    for (int i = 0; i < JPS; i++) {
        int j = s * JPS + i;
        const float4* C = sC4 + j * F4PJ;
        float R1[9], p1[3];
        joint_apply_v(C, sn[i], ic[i], qp[i], R, p, R1, p1);

        bool owner = (((s ^ i) & 1) == 0);
        float Rt[9] = {0}, pt[3] = {0};
        if (owner) {
            float4 t0 = C[13], t1 = C[14], t2 = C[15];
#pragma unroll
            for (int r = 0; r < 3; r++) {
                Rt[r*3+0] = fmaf(R[r*3+0], t0.x, fmaf(R[r*3+1], t1.x, R[r*3+2] * t2.x));
                Rt[r*3+1] = fmaf(R[r*3+0], t0.y, fmaf(R[r*3+1], t1.y, R[r*3+2] * t2.y));
                Rt[r*3+2] = fmaf(R[r*3+0], t0.z, fmaf(R[r*3+1], t1.z, R[r*3+2] * t2.z));
                pt[r] = fmaf(R[r*3+0], t0.w, fmaf(R[r*3+1], t1.w, fmaf(R[r*3+2], t2.w, p[r])));
            }
        }

        if (fast) {
            // stage rev and pri in separate conflict-free 12-stride regions
            float4* spR = (float4*)(stg  + lane * 12);
            float4* spP = (float4*)(stgP + lane * 12);
            spR[0] = make_float4(R1[0], R1[1], R1[2], p1[0]);
            spR[1] = make_float4(R1[3], R1[4], R1[5], p1[1]);
            spR[2] = make_float4(R1[6], R1[7], R1[8], p1[2]);
            spP[0] = make_float4(R[0], R[1], R[2], p[0]);
            spP[1] = make_float4(R[3], R[4], R[5], p[1]);
            spP[2] = make_float4(R[6], R[7], R[8], p[2]);
            __syncwarp();
            float* dR = baseRev + i * 16;
            float* dP = basePri + i * 16;
#pragma unroll
            for (int k = 0; k < 4; k++) {
                int idx = k * 8 + u;
                float4 vr = (m < 3) ? *(const float4*)(stg  + idx * 12 + 4 * m) : hom;
                float4 vp = (m < 3) ? *(const float4*)(stgP + idx * 12 + 4 * m) : hom;
                *(float4*)(dR + k * 640) = vr;
                *(float4*)(dP + k * 640) = vp;
            }
            __syncwarp();
            // track: owners overwrite rev region, then 2-phase drain
            if (owner) {
                float4* tp = (float4*)(stg + lane * 12);
                tp[0] = make_float4(Rt[0], Rt[1], Rt[2], pt[0]);
                tp[1] = make_float4(Rt[3], Rt[4], Rt[5], pt[1]);
                tp[2] = make_float4(Rt[6], Rt[7], Rt[8], pt[2]);
            }
            __syncwarp();
            {
                int s2t  = (i & 1) + 2 * up;
                int slot = (5 * s2t + i) >> 1;
                float* dT = outTrk + ((size_t)(wb0 + uh) * 10 + slot) * 16 + 4 * m;
#pragma unroll
                for (int k = 0; k < 2; k++) {
                    int src = (k * 4 + uh) * 4 + s2t;
                    float4 v = (m < 3) ? *(const float4*)(stg + src * 12 + 4 * m) : hom;
                    *(float4*)(dT + k * 640) = v;
                }
            }
            __syncwarp();
        } else {
            emit_full_g(stg, lane, i, wb0, B, outRev, R1, p1);
            emit_full_g(stg, lane, i, wb0, B, outPri, R, p);
            emit_track_g(stg, lane, i, wb0, B, outTrk, Rt, pt, owner);
        }
    }
}

extern "C" void kernel_launch(void* const* d_in, const int* in_sizes, int n_in,
                              void* d_out, int out_size) {
    const float* rev_q       = (const float*)d_in[0];
    const float* pri_q       = (const float*)d_in[1];
    const float* rev_p_off   = (const float*)d_in[2];
    const float* rev_rpy_off = (const float*)d_in[3];
    const float* pri_p_off   = (const float*)d_in[4];
    const float* pri_rpy_off = (const float*)d_in[5];
    const float* rev_axis    = (const float*)d_in[6];
    const float* pri_axis    = (const float*)d_in[7];
    const float* p_track     = (const float*)d_in[8];
    const float* rpy_track   = (const float*)d_in[9];
    float* out = (float*)d_out;

    int B = in_sizes[0] / J;
    int grid = (B + 31) / 32;
    fk_kernel<<<grid, 128>>>(rev_q, pri_q,
                             rev_p_off, rev_rpy_off, pri_p_off, pri_rpy_off,
                             rev_axis, pri_axis, p_track, rpy_track, out, B);
}